// round 11
// baseline (speedup 1.0000x reference)
#include <cuda_runtime.h>
#include <cuda_fp16.h>
#include <math.h>
#include <stdint.h>

#define TT 256
#define BB 64
#define II 256
#define HH 256
#define NN 8
#define FF 1024   // 4*H

// ---------------- scratch (device globals; no allocs) ----------------
__device__ int g_flags[TT * NN];
__device__ __align__(16) __half g_xf[(size_t)TT * BB * II];   // X fp16 [m][k]
// h exchange, parity double-buffered: [p][n][b][k] fp16
__device__ __align__(16) __half g_hf[2 * NN * BB * HH];

extern __shared__ char dynsmem[];

// ---------------- helpers ----------------
__device__ __forceinline__ uint32_t smem_u32(const void* p) {
    uint32_t a;
    asm("{ .reg .u64 t; cvta.to.shared.u64 t, %1; cvt.u32.u64 %0, t; }" : "=r"(a) : "l"(p));
    return a;
}

__device__ __forceinline__ void ldsm_x4(uint32_t* r, uint32_t addr) {
    asm volatile("ldmatrix.sync.aligned.m8n8.x4.shared.b16 {%0,%1,%2,%3}, [%4];"
                 : "=r"(r[0]), "=r"(r[1]), "=r"(r[2]), "=r"(r[3]) : "r"(addr));
}

__device__ __forceinline__ void mma_f16(float* c, const uint32_t* a,
                                        uint32_t b0, uint32_t b1) {
    asm volatile(
        "mma.sync.aligned.m16n8k16.row.col.f32.f16.f16.f32 "
        "{%0,%1,%2,%3}, {%4,%5,%6,%7}, {%8,%9}, {%0,%1,%2,%3};"
        : "+f"(c[0]), "+f"(c[1]), "+f"(c[2]), "+f"(c[3])
        : "r"(a[0]), "r"(a[1]), "r"(a[2]), "r"(a[3]), "r"(b0), "r"(b1));
}

__device__ __forceinline__ float fast_sigmoid(float x) {
    return __fdividef(1.f, 1.f + __expf(-x));
}
__device__ __forceinline__ float fast_tanh(float x) {
    return 1.f - __fdividef(2.f, __expf(2.f * x) + 1.f);
}

// ---------------------------------------------------------------------------
// conv_x: X fp32 -> fp16. Also zeroes g_flags.
// ---------------------------------------------------------------------------
__global__ __launch_bounds__(256) void conv_x(const float* __restrict__ x) {
    if (blockIdx.x < 8) g_flags[blockIdx.x * 256 + threadIdx.x] = 0;
    const size_t i0 = ((size_t)blockIdx.x * 256 + threadIdx.x) * 4;
    const float4 v = *(const float4*)(x + i0);
    __half hv[4];
    hv[0] = __float2half(v.x); hv[1] = __float2half(v.y);
    hv[2] = __float2half(v.z); hv[3] = __float2half(v.w);
    *reinterpret_cast<uint2*>(g_xf + i0) = *reinterpret_cast<uint2*>(hv);
}

// ---------------------------------------------------------------------------
// recur_kernel: fused persistent LSTM, fp16 2-product HMMA.
// 128 CTAs (jt, n), 512 threads = 16 warps (4 b-quarters x 4 c-quarters).
// Per step:  z = X(t) @ Wx + h(t-1) @ Wh + bias;  a·w ~= a·wh + a·wl.
// Pipeline: spin -> issue h cp.async -> x-GEMM(t) (hides h L2 fetch) ->
//           wait -> h-GEMM -> stage -> prefetch X(t+1) -> epilogue -> publish.
// c ordering: c = 4*hl + gate  ->  f = gate*H + jt*16 + hl.
// ---------------------------------------------------------------------------
#define WSTR   264                  // fp16 elems per smem row (256 + 8 pad)
#define S_WXH  0
#define S_WXL  33792
#define S_WHH  67584
#define S_WHL  101376
#define S_XB   135168
#define S_HB   168960
#define S_ZS   202752               // 64*68*4 = 17408
#define S_TOT  220160

__device__ __forceinline__ void gemm2_acc(
    float acc[2][4], uint32_t sbase, uint32_t aB,
    uint32_t bH, uint32_t bL,
    int a_row, int a_kof, int b_row, int b_kof)
{
#pragma unroll 4
    for (int ks = 0; ks < 16; ks++) {
        const int k0 = ks * 16;
        uint32_t a[4], bh[4], bl[4];
        ldsm_x4(a,  sbase + aB + (a_row * WSTR + k0 + a_kof) * 2);
        ldsm_x4(bh, sbase + bH + (b_row * WSTR + k0 + b_kof) * 2);
        ldsm_x4(bl, sbase + bL + (b_row * WSTR + k0 + b_kof) * 2);
#pragma unroll
        for (int nf = 0; nf < 2; nf++) {
            mma_f16(acc[nf], a, bh[nf * 2], bh[nf * 2 + 1]);
            mma_f16(acc[nf], a, bl[nf * 2], bl[nf * 2 + 1]);
        }
    }
}

__global__ __launch_bounds__(512, 1) void recur_kernel(
    const float* __restrict__ w,    // [N, I+H, FF]
    const float* __restrict__ bi,   // [N, FF]
    const float* __restrict__ bh_,  // [N, FF]
    const int*   __restrict__ fd,   // [T*B]
    float* out)                     // [T, N, B, H]
{
    char* sm = dynsmem;
    const uint32_t sbase = smem_u32(sm);
    __half* Wxh = (__half*)(sm + S_WXH);
    __half* Wxl = (__half*)(sm + S_WXL);
    __half* Whh = (__half*)(sm + S_WHH);
    __half* Whl = (__half*)(sm + S_WHL);
    float* Zs = (float*)(sm + S_ZS);     // [64][68]

    const int jt = blockIdx.x & 15;
    const int n  = blockIdx.x >> 4;
    const int tid = threadIdx.x;
    const int wid = tid >> 5, lane = tid & 31;
    const int tx = tid & 15;
    const int ty = tid >> 4;             // 0..31

    // warp tiling: mw = b-quarter (16 rows), nw = c-quarter (16 cols)
    const int mw = wid & 3, nw = wid >> 2;
    const int lrow = lane & 7, lgrp = lane >> 3;
    const int a_row = mw * 16 + (lgrp & 1) * 8 + lrow;
    const int a_kof = (lgrp >> 1) * 8;
    const int b_row = nw * 16 + (lgrp >> 1) * 8 + lrow;
    const int b_kof = (lgrp & 1) * 8;

    // ---- issue X(0) load first (overlaps weight conversion) ----
    {
#pragma unroll
        for (int i = 0; i < 4; i++) {
            const int id = tid + 512 * i, r = id >> 5, ch = id & 31;
            asm volatile("cp.async.ca.shared.global [%0], [%1], 16;\n"
                         :: "r"(sbase + S_XB + r * 528 + ch * 16),
                            "l"((const void*)(g_xf + (size_t)r * II + ch * 8)));
        }
        asm volatile("cp.async.commit_group;\n");
    }

    // ---- prologue: convert Wx and Wh slices (fp32 -> fp16 hi/lo, K-major) ----
    const float* wx = w + (size_t)n * (II + HH) * FF;            // k in [0,256)
    const float* wh = wx + (size_t)II * FF;                      // k in [256,512)
    for (int i = tid; i < 64 * 256; i += 512) {
        const int k = i >> 6, q = i & 63;
        const int g = q >> 4, hl = q & 15;
        const int c = 4 * hl + g;
        const size_t col = (size_t)g * HH + jt * 16 + hl;
        {
            const float v = wx[(size_t)k * FF + col];
            const __half h = __float2half(v);
            Wxh[c * WSTR + k] = h;
            Wxl[c * WSTR + k] = __float2half(v - __half2float(h));
        }
        {
            const float v = wh[(size_t)k * FF + col];
            const __half h = __float2half(v);
            Whh[c * WSTR + k] = h;
            Whl[c * WSTR + k] = __float2half(v - __half2float(h));
        }
    }

    // bias registers: thread's column j, 4 gates
    const int j = jt * 16 + tx;
    float bias4[4];
#pragma unroll
    for (int g = 0; g < 4; g++)
        bias4[g] = bi[(size_t)n * FF + g * HH + j] + bh_[(size_t)n * FF + g * HH + j];

    float creg[2] = {0.f, 0.f};          // rows b = 2*ty + r
    __syncthreads();                     // weights visible

    for (int t = 0; t < TT; t++) {
        if (t > 0) {
            // all threads spin on the branch flag
            int v;
            do {
                asm volatile("ld.acquire.gpu.global.s32 %0, [%1];"
                             : "=r"(v) : "l"(g_flags + (t - 1) * NN + n));
            } while (v < 16);

            // issue cp.async h(t-1) -> HB (latency hidden behind x-GEMM below)
            const __half* sh = g_hf + ((size_t)((t - 1) & 1) * NN + n) * BB * HH;
#pragma unroll
            for (int i = 0; i < 4; i++) {
                const int id = tid + 512 * i, r = id >> 5, ch = id & 31;
                asm volatile("cp.async.ca.shared.global [%0], [%1], 16;\n"
                             :: "r"(sbase + S_HB + r * 528 + ch * 16),
                                "l"((const void*)(sh + (size_t)r * HH + ch * 8)));
            }
            asm volatile("cp.async.commit_group;\n");
        }

        // XB(t) ready? (older group). t=0: only XB pending; t>0: XB older, HB newer.
        if (t == 0) asm volatile("cp.async.wait_group 0;\n" ::: "memory");
        else        asm volatile("cp.async.wait_group 1;\n" ::: "memory");
        __syncthreads();

        // -- x-GEMM(t): hides the HB fetch --
        float acc[2][4];
#pragma unroll
        for (int nf = 0; nf < 2; nf++)
#pragma unroll
            for (int q = 0; q < 4; q++) acc[nf][q] = 0.f;
        gemm2_acc(acc, sbase, S_XB, S_WXH, S_WXL, a_row, a_kof, b_row, b_kof);

        if (t > 0) {
            asm volatile("cp.async.wait_group 0;\n" ::: "memory");
            __syncthreads();
            gemm2_acc(acc, sbase, S_HB, S_WHH, S_WHL, a_row, a_kof, b_row, b_kof);
        }

        // -- stage z fragments into Zs[b][c] --
#pragma unroll
        for (int nf = 0; nf < 2; nf++) {
            const int row = mw * 16 + (lane >> 2);
            const int col = nw * 16 + nf * 8 + (lane & 3) * 2;
            *(float2*)(Zs + row * 68 + col) = make_float2(acc[nf][0], acc[nf][1]);
            *(float2*)(Zs + (row + 8) * 68 + col) = make_float2(acc[nf][2], acc[nf][3]);
        }
        __syncthreads();

        // -- prefetch X(t+1) into XB (XB free; consumed next iteration) --
        if (t + 1 < TT) {
            const __half* xs = g_xf + (size_t)(t + 1) * BB * II;
#pragma unroll
            for (int i = 0; i < 4; i++) {
                const int id = tid + 512 * i, r = id >> 5, ch = id & 31;
                asm volatile("cp.async.ca.shared.global [%0], [%1], 16;\n"
                             :: "r"(sbase + S_XB + r * 528 + ch * 16),
                                "l"((const void*)(xs + (size_t)r * II + ch * 8)));
            }
            asm volatile("cp.async.commit_group;\n");
        }

        // -- LSTM epilogue; publish h(t) fp32 (out) + fp16 (exchange) --
        __half* hb = g_hf + ((size_t)(t & 1) * NN + n) * BB * HH;
        const int2 dur2 = *(const int2*)(fd + t * BB + 2 * ty);
        const int durs[2] = {dur2.x, dur2.y};
#pragma unroll
        for (int r = 0; r < 2; r++) {
            const int b = 2 * ty + r;
            const float4 zh = *(const float4*)(Zs + b * 68 + 4 * tx);  // i,f,o,g
            const float zi  = zh.x + bias4[0];
            const float zf_ = zh.y + bias4[1];
            const float zo  = zh.z + bias4[2];
            const float zg_ = zh.w + bias4[3];

            const bool keep = (n > (durs[r] >> 3));

            const float ig = fast_sigmoid(zi);
            const float fg = fast_sigmoid(zf_);
            const float og = fast_sigmoid(zo);
            const float gg = fast_tanh(zg_);

            float cn = fg * creg[r] + ig * gg;
            cn = keep ? creg[r] : cn;
            creg[r] = cn;
            const float hn = og * fast_tanh(cn);

            out[((size_t)(t * NN + n) * BB + b) * HH + j] = hn;
            hb[b * HH + j] = __float2half(hn);
        }

        __syncthreads();   // Zs reads done; h stores issued by all threads

        if (tid == 0) {
            asm volatile("red.release.gpu.global.add.s32 [%0], %1;"
                         :: "l"(g_flags + t * NN + n), "r"(1) : "memory");
        }
    }
}

// ---------------------------------------------------------------------------
extern "C" void kernel_launch(void* const* d_in, const int* in_sizes, int n_in,
                              void* d_out, int out_size)
{
    const float* x  = (const float*)d_in[0];   // [T,B,I] f32
    const int*   fd = (const int*)  d_in[1];   // [T,B]   i32
    const float* w  = (const float*)d_in[2];   // [N,I+H,4H] f32
    const float* bi = (const float*)d_in[3];   // [N,4H]
    const float* bh = (const float*)d_in[4];   // [N,4H]
    float* out = (float*)d_out;                // [T,N,B,H]

    conv_x<<<4096, 256>>>(x);

    cudaFuncSetAttribute(recur_kernel, cudaFuncAttributeMaxDynamicSharedMemorySize,
                         S_TOT);
    recur_kernel<<<128, 512, S_TOT>>>(w, bi, bh, fd, out);
}

// round 12
// speedup vs baseline: 1.1542x; 1.1542x over previous
#include <cuda_runtime.h>
#include <cuda_fp16.h>
#include <math.h>
#include <stdint.h>

#define TT 256
#define BB 64
#define II 256
#define HH 256
#define NN 8
#define FF 1024   // 4*H

// ---------------- scratch (device globals; no allocs) ----------------
__device__ int g_flags[TT * NN];
__device__ __align__(16) __half g_xf[(size_t)TT * BB * II];   // X fp16 [m][k]
// h exchange, parity double-buffered: [p][n][b][k] fp16
__device__ __align__(16) __half g_hf[2 * NN * BB * HH];

extern __shared__ char dynsmem[];

// ---------------- helpers ----------------
__device__ __forceinline__ uint32_t smem_u32(const void* p) {
    uint32_t a;
    asm("{ .reg .u64 t; cvta.to.shared.u64 t, %1; cvt.u32.u64 %0, t; }" : "=r"(a) : "l"(p));
    return a;
}

__device__ __forceinline__ void ldsm_x4(uint32_t* r, uint32_t addr) {
    asm volatile("ldmatrix.sync.aligned.m8n8.x4.shared.b16 {%0,%1,%2,%3}, [%4];"
                 : "=r"(r[0]), "=r"(r[1]), "=r"(r[2]), "=r"(r[3]) : "r"(addr));
}

__device__ __forceinline__ void mma_f16(float* c, const uint32_t* a,
                                        uint32_t b0, uint32_t b1) {
    asm volatile(
        "mma.sync.aligned.m16n8k16.row.col.f32.f16.f16.f32 "
        "{%0,%1,%2,%3}, {%4,%5,%6,%7}, {%8,%9}, {%0,%1,%2,%3};"
        : "+f"(c[0]), "+f"(c[1]), "+f"(c[2]), "+f"(c[3])
        : "r"(a[0]), "r"(a[1]), "r"(a[2]), "r"(a[3]), "r"(b0), "r"(b1));
}

__device__ __forceinline__ float fast_sigmoid(float x) {
    return __fdividef(1.f, 1.f + __expf(-x));
}
__device__ __forceinline__ float fast_tanh(float x) {
    return 1.f - __fdividef(2.f, __expf(2.f * x) + 1.f);
}

// ---------------------------------------------------------------------------
// conv_x: X fp32 -> fp16. Also zeroes g_flags.
// ---------------------------------------------------------------------------
__global__ __launch_bounds__(256) void conv_x(const float* __restrict__ x) {
    if (blockIdx.x < 8) g_flags[blockIdx.x * 256 + threadIdx.x] = 0;
    const size_t i0 = ((size_t)blockIdx.x * 256 + threadIdx.x) * 4;
    const float4 v = *(const float4*)(x + i0);
    __half hv[4];
    hv[0] = __float2half(v.x); hv[1] = __float2half(v.y);
    hv[2] = __float2half(v.z); hv[3] = __float2half(v.w);
    *reinterpret_cast<uint2*>(g_xf + i0) = *reinterpret_cast<uint2*>(hv);
}

// ---------------------------------------------------------------------------
// recur_kernel: fused persistent LSTM, fp16 2-product HMMA.
// 128 CTAs (jt, n), 256 threads = 8 warps (2 b-halves x 4 c-quarters) — the
// R10 tiling. Pipeline per step (the only change vs R10):
//   spin -> issue HB cp.async -> x-GEMM(t) from XB (covers HB L2 fetch) ->
//   wait -> h-GEMM -> stage -> prefetch XB(t+1) -> epilogue -> publish.
// c ordering: c = 4*hl + gate  ->  f = gate*H + jt*16 + hl.
// ---------------------------------------------------------------------------
#define WSTR   264                  // fp16 elems per smem row (256 + 8 pad)
#define S_WXH  0
#define S_WXL  33792
#define S_WHH  67584
#define S_WHL  101376
#define S_XB   135168
#define S_HB   168960
#define S_ZS   202752               // 64*68*4 = 17408
#define S_TOT  220160

__device__ __forceinline__ void gemm2_acc(
    float acc[2][2][4], uint32_t sbase, uint32_t aB,
    uint32_t bH, uint32_t bL,
    int a_row, int a_kof, int b_row, int b_kof)
{
#pragma unroll 4
    for (int ks = 0; ks < 16; ks++) {
        const int k0 = ks * 16;
        uint32_t a[2][4], bh[4], bl[4];
#pragma unroll
        for (int ma = 0; ma < 2; ma++)
            ldsm_x4(a[ma], sbase + aB + ((a_row + ma * 16) * WSTR + k0 + a_kof) * 2);
        ldsm_x4(bh, sbase + bH + (b_row * WSTR + k0 + b_kof) * 2);
        ldsm_x4(bl, sbase + bL + (b_row * WSTR + k0 + b_kof) * 2);
#pragma unroll
        for (int ma = 0; ma < 2; ma++)
#pragma unroll
            for (int nf = 0; nf < 2; nf++) {
                mma_f16(acc[ma][nf], a[ma], bh[nf * 2], bh[nf * 2 + 1]);
                mma_f16(acc[ma][nf], a[ma], bl[nf * 2], bl[nf * 2 + 1]);
            }
    }
}

__global__ __launch_bounds__(256, 1) void recur_kernel(
    const float* __restrict__ w,    // [N, I+H, FF]
    const float* __restrict__ bi,   // [N, FF]
    const float* __restrict__ bh_,  // [N, FF]
    const int*   __restrict__ fd,   // [T*B]
    float* out)                     // [T, N, B, H]
{
    char* sm = dynsmem;
    const uint32_t sbase = smem_u32(sm);
    __half* Wxh = (__half*)(sm + S_WXH);
    __half* Wxl = (__half*)(sm + S_WXL);
    __half* Whh = (__half*)(sm + S_WHH);
    __half* Whl = (__half*)(sm + S_WHL);
    float* Zs = (float*)(sm + S_ZS);     // [64][68]

    const int jt = blockIdx.x & 15;
    const int n  = blockIdx.x >> 4;
    const int tid = threadIdx.x;
    const int wid = tid >> 5, lane = tid & 31;
    const int tx = tid & 15;
    const int ty = tid >> 4;

    // warp tiling: mw = b-half (32 rows, 2 ma tiles), nw = c-quarter (16)
    const int mw = wid & 1, nw = wid >> 1;
    const int lrow = lane & 7, lgrp = lane >> 3;
    const int a_row = mw * 32 + (lgrp & 1) * 8 + lrow;   // + ma*16
    const int a_kof = (lgrp >> 1) * 8;
    const int b_row = nw * 16 + (lgrp >> 1) * 8 + lrow;
    const int b_kof = (lgrp & 1) * 8;

    // ---- issue X(0) load first (overlaps weight conversion) ----
    {
#pragma unroll
        for (int i = 0; i < 8; i++) {
            const int id = tid + 256 * i, r = id >> 5, ch = id & 31;
            asm volatile("cp.async.ca.shared.global [%0], [%1], 16;\n"
                         :: "r"(sbase + S_XB + r * 528 + ch * 16),
                            "l"((const void*)(g_xf + (size_t)r * II + ch * 8)));
        }
        asm volatile("cp.async.commit_group;\n");
    }

    // ---- prologue: convert Wx and Wh slices (fp32 -> fp16 hi/lo, K-major) ----
    const float* wx = w + (size_t)n * (II + HH) * FF;            // k in [0,256)
    const float* wh = wx + (size_t)II * FF;                      // k in [256,512)
    for (int i = tid; i < 64 * 256; i += 256) {
        const int k = i >> 6, q = i & 63;
        const int g = q >> 4, hl = q & 15;
        const int c = 4 * hl + g;
        const size_t col = (size_t)g * HH + jt * 16 + hl;
        {
            const float v = wx[(size_t)k * FF + col];
            const __half h = __float2half(v);
            Wxh[c * WSTR + k] = h;
            Wxl[c * WSTR + k] = __float2half(v - __half2float(h));
        }
        {
            const float v = wh[(size_t)k * FF + col];
            const __half h = __float2half(v);
            Whh[c * WSTR + k] = h;
            Whl[c * WSTR + k] = __float2half(v - __half2float(h));
        }
    }

    // bias registers: thread's column j, 4 gates
    const int j = jt * 16 + tx;
    float bias4[4];
#pragma unroll
    for (int g = 0; g < 4; g++)
        bias4[g] = bi[(size_t)n * FF + g * HH + j] + bh_[(size_t)n * FF + g * HH + j];

    float creg[4] = {0.f, 0.f, 0.f, 0.f};   // rows b = 4*ty + r
    __syncthreads();                         // weights visible

    for (int t = 0; t < TT; t++) {
        if (t > 0) {
            // all threads spin on the branch flag
            int v;
            do {
                asm volatile("ld.acquire.gpu.global.s32 %0, [%1];"
                             : "=r"(v) : "l"(g_flags + (t - 1) * NN + n));
            } while (v < 16);

            // issue cp.async h(t-1) -> HB (latency hidden behind x-GEMM below)
            const __half* sh = g_hf + ((size_t)((t - 1) & 1) * NN + n) * BB * HH;
#pragma unroll
            for (int i = 0; i < 8; i++) {
                const int id = tid + 256 * i, r = id >> 5, ch = id & 31;
                asm volatile("cp.async.ca.shared.global [%0], [%1], 16;\n"
                             :: "r"(sbase + S_HB + r * 528 + ch * 16),
                                "l"((const void*)(sh + (size_t)r * HH + ch * 8)));
            }
            asm volatile("cp.async.commit_group;\n");
        }

        // XB(t) ready? (older group). t=0: only XB pending; t>0: XB older, HB newer.
        if (t == 0) asm volatile("cp.async.wait_group 0;\n" ::: "memory");
        else        asm volatile("cp.async.wait_group 1;\n" ::: "memory");
        __syncthreads();

        // -- x-GEMM(t): covers the HB L2 fetch --
        float acc[2][2][4];
#pragma unroll
        for (int ma = 0; ma < 2; ma++)
#pragma unroll
            for (int nf = 0; nf < 2; nf++)
#pragma unroll
                for (int q = 0; q < 4; q++) acc[ma][nf][q] = 0.f;
        gemm2_acc(acc, sbase, S_XB, S_WXH, S_WXL, a_row, a_kof, b_row, b_kof);

        if (t > 0) {
            asm volatile("cp.async.wait_group 0;\n" ::: "memory");
            __syncthreads();
            gemm2_acc(acc, sbase, S_HB, S_WHH, S_WHL, a_row, a_kof, b_row, b_kof);
        }

        // -- stage z fragments into Zs[b][c] --
#pragma unroll
        for (int ma = 0; ma < 2; ma++)
#pragma unroll
            for (int nf = 0; nf < 2; nf++) {
                const int row = mw * 32 + ma * 16 + (lane >> 2);
                const int col = nw * 16 + nf * 8 + (lane & 3) * 2;
                *(float2*)(Zs + row * 68 + col) =
                    make_float2(acc[ma][nf][0], acc[ma][nf][1]);
                *(float2*)(Zs + (row + 8) * 68 + col) =
                    make_float2(acc[ma][nf][2], acc[ma][nf][3]);
            }
        __syncthreads();

        // -- prefetch X(t+1) into XB (XB free; consumed next iteration) --
        if (t + 1 < TT) {
            const __half* xs = g_xf + (size_t)(t + 1) * BB * II;
#pragma unroll
            for (int i = 0; i < 8; i++) {
                const int id = tid + 256 * i, r = id >> 5, ch = id & 31;
                asm volatile("cp.async.ca.shared.global [%0], [%1], 16;\n"
                             :: "r"(sbase + S_XB + r * 528 + ch * 16),
                                "l"((const void*)(xs + (size_t)r * II + ch * 8)));
            }
            asm volatile("cp.async.commit_group;\n");
        }

        // -- LSTM epilogue; publish h(t) fp32 (out) + fp16 (exchange) --
        __half* hb = g_hf + ((size_t)(t & 1) * NN + n) * BB * HH;
        const int4 dur4 = *(const int4*)(fd + t * BB + 4 * ty);
        const int durs[4] = {dur4.x, dur4.y, dur4.z, dur4.w};
#pragma unroll
        for (int r = 0; r < 4; r++) {
            const int b = 4 * ty + r;
            const float4 zh = *(const float4*)(Zs + b * 68 + 4 * tx);  // i,f,o,g
            const float zi  = zh.x + bias4[0];
            const float zf_ = zh.y + bias4[1];
            const float zo  = zh.z + bias4[2];
            const float zg_ = zh.w + bias4[3];

            const bool keep = (n > (durs[r] >> 3));

            const float ig = fast_sigmoid(zi);
            const float fg = fast_sigmoid(zf_);
            const float og = fast_sigmoid(zo);
            const float gg = fast_tanh(zg_);

            float cn = fg * creg[r] + ig * gg;
            cn = keep ? creg[r] : cn;
            creg[r] = cn;
            const float hn = og * fast_tanh(cn);

            out[((size_t)(t * NN + n) * BB + b) * HH + j] = hn;
            hb[b * HH + j] = __float2half(hn);
        }

        __syncthreads();   // Zs reads done; h stores issued by all threads

        if (tid == 0) {
            asm volatile("red.release.gpu.global.add.s32 [%0], %1;"
                         :: "l"(g_flags + t * NN + n), "r"(1) : "memory");
        }
    }
}

// ---------------------------------------------------------------------------
extern "C" void kernel_launch(void* const* d_in, const int* in_sizes, int n_in,
                              void* d_out, int out_size)
{
    const float* x  = (const float*)d_in[0];   // [T,B,I] f32
    const int*   fd = (const int*)  d_in[1];   // [T,B]   i32
    const float* w  = (const float*)d_in[2];   // [N,I+H,4H] f32
    const float* bi = (const float*)d_in[3];   // [N,4H]
    const float* bh = (const float*)d_in[4];   // [N,4H]
    float* out = (float*)d_out;                // [T,N,B,H]

    conv_x<<<4096, 256>>>(x);

    cudaFuncSetAttribute(recur_kernel, cudaFuncAttributeMaxDynamicSharedMemorySize,
                         S_TOT);
    recur_kernel<<<128, 256, S_TOT>>>(w, bi, bh, fd, out);
}

// round 13
// speedup vs baseline: 1.2578x; 1.0897x over previous
#include <cuda_runtime.h>
#include <cuda_fp16.h>
#include <math.h>
#include <stdint.h>

#define TT 256
#define BB 64
#define II 256
#define HH 256
#define NN 8
#define FF 1024   // 4*H

// ---------------- scratch (device globals; no allocs) ----------------
__device__ int g_flags[TT * NN];
__device__ __align__(16) __half g_xf[(size_t)TT * BB * II];   // X fp16 [m][k]
// h exchange, parity double-buffered: [p][n][b][k] fp16
__device__ __align__(16) __half g_hf[2 * NN * BB * HH];

extern __shared__ char dynsmem[];

// ---------------- helpers ----------------
__device__ __forceinline__ uint32_t smem_u32(const void* p) {
    uint32_t a;
    asm("{ .reg .u64 t; cvta.to.shared.u64 t, %1; cvt.u32.u64 %0, t; }" : "=r"(a) : "l"(p));
    return a;
}

__device__ __forceinline__ void ldsm_x4(uint32_t* r, uint32_t addr) {
    asm volatile("ldmatrix.sync.aligned.m8n8.x4.shared.b16 {%0,%1,%2,%3}, [%4];"
                 : "=r"(r[0]), "=r"(r[1]), "=r"(r[2]), "=r"(r[3]) : "r"(addr));
}

__device__ __forceinline__ void mma_f16(float* c, const uint32_t* a,
                                        uint32_t b0, uint32_t b1) {
    asm volatile(
        "mma.sync.aligned.m16n8k16.row.col.f32.f16.f16.f32 "
        "{%0,%1,%2,%3}, {%4,%5,%6,%7}, {%8,%9}, {%0,%1,%2,%3};"
        : "+f"(c[0]), "+f"(c[1]), "+f"(c[2]), "+f"(c[3])
        : "r"(a[0]), "r"(a[1]), "r"(a[2]), "r"(a[3]), "r"(b0), "r"(b1));
}

__device__ __forceinline__ float fast_sigmoid(float x) {
    return __fdividef(1.f, 1.f + __expf(-x));
}
__device__ __forceinline__ float fast_tanh(float x) {
    return 1.f - __fdividef(2.f, __expf(2.f * x) + 1.f);
}

// ---------------------------------------------------------------------------
// conv_x: X fp32 -> fp16. Also zeroes g_flags.
// ---------------------------------------------------------------------------
__global__ __launch_bounds__(256) void conv_x(const float* __restrict__ x) {
    if (blockIdx.x < 8) g_flags[blockIdx.x * 256 + threadIdx.x] = 0;
    const size_t i0 = ((size_t)blockIdx.x * 256 + threadIdx.x) * 4;
    const float4 v = *(const float4*)(x + i0);
    __half hv[4];
    hv[0] = __float2half(v.x); hv[1] = __float2half(v.y);
    hv[2] = __float2half(v.z); hv[3] = __float2half(v.w);
    *reinterpret_cast<uint2*>(g_xf + i0) = *reinterpret_cast<uint2*>(hv);
}

// ---------------------------------------------------------------------------
// recur_kernel: fused persistent LSTM, fp16 2-product HMMA.
// 128 CTAs (jt, n), 256 threads = 8 warps (2 b-halves x 4 c-quarters).
// R10 structure with the x-GEMM SPLIT across the sync point:
//   ... publish(t-1) -> x-GEMM(t) ks 0-7 (absorbs CTA skew) -> spin(t-1) ->
//   issue HB cp.async -> x-GEMM(t) ks 8-15 (covers HB fetch) -> wait ->
//   h-GEMM -> stage -> prefetch XB(t+1) -> epilogue -> publish(t).
// c ordering: c = 4*hl + gate  ->  f = gate*H + jt*16 + hl.
// ---------------------------------------------------------------------------
#define WSTR   264                  // fp16 elems per smem row (256 + 8 pad)
#define S_WXH  0
#define S_WXL  33792
#define S_WHH  67584
#define S_WHL  101376
#define S_XB   135168
#define S_HB   168960
#define S_ZS   202752               // 64*68*4 = 17408
#define S_TOT  220160

__device__ __forceinline__ void gemm2_acc(
    float acc[2][2][4], uint32_t sbase, uint32_t aB,
    uint32_t bH, uint32_t bL,
    int a_row, int a_kof, int b_row, int b_kof,
    int ks_begin, int ks_end)
{
#pragma unroll 4
    for (int ks = ks_begin; ks < ks_end; ks++) {
        const int k0 = ks * 16;
        uint32_t a[2][4], bh[4], bl[4];
#pragma unroll
        for (int ma = 0; ma < 2; ma++)
            ldsm_x4(a[ma], sbase + aB + ((a_row + ma * 16) * WSTR + k0 + a_kof) * 2);
        ldsm_x4(bh, sbase + bH + (b_row * WSTR + k0 + b_kof) * 2);
        ldsm_x4(bl, sbase + bL + (b_row * WSTR + k0 + b_kof) * 2);
#pragma unroll
        for (int ma = 0; ma < 2; ma++)
#pragma unroll
            for (int nf = 0; nf < 2; nf++) {
                mma_f16(acc[ma][nf], a[ma], bh[nf * 2], bh[nf * 2 + 1]);
                mma_f16(acc[ma][nf], a[ma], bl[nf * 2], bl[nf * 2 + 1]);
            }
    }
}

__global__ __launch_bounds__(256, 1) void recur_kernel(
    const float* __restrict__ w,    // [N, I+H, FF]
    const float* __restrict__ bi,   // [N, FF]
    const float* __restrict__ bh_,  // [N, FF]
    const int*   __restrict__ fd,   // [T*B]
    float* out)                     // [T, N, B, H]
{
    char* sm = dynsmem;
    const uint32_t sbase = smem_u32(sm);
    __half* Wxh = (__half*)(sm + S_WXH);
    __half* Wxl = (__half*)(sm + S_WXL);
    __half* Whh = (__half*)(sm + S_WHH);
    __half* Whl = (__half*)(sm + S_WHL);
    float* Zs = (float*)(sm + S_ZS);     // [64][68]

    const int jt = blockIdx.x & 15;
    const int n  = blockIdx.x >> 4;
    const int tid = threadIdx.x;
    const int wid = tid >> 5, lane = tid & 31;
    const int tx = tid & 15;
    const int ty = tid >> 4;

    // warp tiling: mw = b-half (32 rows, 2 ma tiles), nw = c-quarter (16)
    const int mw = wid & 1, nw = wid >> 1;
    const int lrow = lane & 7, lgrp = lane >> 3;
    const int a_row = mw * 32 + (lgrp & 1) * 8 + lrow;   // + ma*16
    const int a_kof = (lgrp >> 1) * 8;
    const int b_row = nw * 16 + (lgrp >> 1) * 8 + lrow;
    const int b_kof = (lgrp & 1) * 8;

    // ---- issue X(0) load first (overlaps weight conversion) ----
    {
#pragma unroll
        for (int i = 0; i < 8; i++) {
            const int id = tid + 256 * i, r = id >> 5, ch = id & 31;
            asm volatile("cp.async.ca.shared.global [%0], [%1], 16;\n"
                         :: "r"(sbase + S_XB + r * 528 + ch * 16),
                            "l"((const void*)(g_xf + (size_t)r * II + ch * 8)));
        }
        asm volatile("cp.async.commit_group;\n");
    }

    // ---- prologue: convert Wx and Wh slices (fp32 -> fp16 hi/lo, K-major) ----
    const float* wx = w + (size_t)n * (II + HH) * FF;            // k in [0,256)
    const float* wh = wx + (size_t)II * FF;                      // k in [256,512)
    for (int i = tid; i < 64 * 256; i += 256) {
        const int k = i >> 6, q = i & 63;
        const int g = q >> 4, hl = q & 15;
        const int c = 4 * hl + g;
        const size_t col = (size_t)g * HH + jt * 16 + hl;
        {
            const float v = wx[(size_t)k * FF + col];
            const __half h = __float2half(v);
            Wxh[c * WSTR + k] = h;
            Wxl[c * WSTR + k] = __float2half(v - __half2float(h));
        }
        {
            const float v = wh[(size_t)k * FF + col];
            const __half h = __float2half(v);
            Whh[c * WSTR + k] = h;
            Whl[c * WSTR + k] = __float2half(v - __half2float(h));
        }
    }

    // bias registers: thread's column j, 4 gates
    const int j = jt * 16 + tx;
    float bias4[4];
#pragma unroll
    for (int g = 0; g < 4; g++)
        bias4[g] = bi[(size_t)n * FF + g * HH + j] + bh_[(size_t)n * FF + g * HH + j];

    float creg[4] = {0.f, 0.f, 0.f, 0.f};   // rows b = 4*ty + r
    __syncthreads();                         // weights visible

    // XB(0) ready, then first-half x-GEMM(0)
    asm volatile("cp.async.wait_group 0;\n" ::: "memory");
    __syncthreads();

    float acc[2][2][4];
#pragma unroll
    for (int ma = 0; ma < 2; ma++)
#pragma unroll
        for (int nf = 0; nf < 2; nf++)
#pragma unroll
            for (int q = 0; q < 4; q++) acc[ma][nf][q] = 0.f;
    gemm2_acc(acc, sbase, S_XB, S_WXH, S_WXL, a_row, a_kof, b_row, b_kof, 0, 8);

    for (int t = 0; t < TT; t++) {
        if (t > 0) {
            // spin on the branch flag (x-half-1 already absorbed most skew)
            int v;
            do {
                asm volatile("ld.acquire.gpu.global.s32 %0, [%1];"
                             : "=r"(v) : "l"(g_flags + (t - 1) * NN + n));
            } while (v < 16);

            // issue cp.async h(t-1) -> HB; latency covered by x-half-2 below
            const __half* sh = g_hf + ((size_t)((t - 1) & 1) * NN + n) * BB * HH;
#pragma unroll
            for (int i = 0; i < 8; i++) {
                const int id = tid + 256 * i, r = id >> 5, ch = id & 31;
                asm volatile("cp.async.ca.shared.global [%0], [%1], 16;\n"
                             :: "r"(sbase + S_HB + r * 528 + ch * 16),
                                "l"((const void*)(sh + (size_t)r * HH + ch * 8)));
            }
            asm volatile("cp.async.commit_group;\n");
        }

        // -- x-GEMM(t) second half: covers the HB L2 fetch --
        gemm2_acc(acc, sbase, S_XB, S_WXH, S_WXL, a_row, a_kof, b_row, b_kof, 8, 16);

        if (t > 0) {
            asm volatile("cp.async.wait_group 0;\n" ::: "memory");
            __syncthreads();
            gemm2_acc(acc, sbase, S_HB, S_WHH, S_WHL, a_row, a_kof, b_row, b_kof, 0, 16);
        }

        // -- stage z fragments into Zs[b][c] --
#pragma unroll
        for (int ma = 0; ma < 2; ma++)
#pragma unroll
            for (int nf = 0; nf < 2; nf++) {
                const int row = mw * 32 + ma * 16 + (lane >> 2);
                const int col = nw * 16 + nf * 8 + (lane & 3) * 2;
                *(float2*)(Zs + row * 68 + col) =
                    make_float2(acc[ma][nf][0], acc[ma][nf][1]);
                *(float2*)(Zs + (row + 8) * 68 + col) =
                    make_float2(acc[ma][nf][2], acc[ma][nf][3]);
            }
        __syncthreads();

        // -- prefetch X(t+1) into XB (XB free; consumed later this iteration) --
        if (t + 1 < TT) {
            const __half* xs = g_xf + (size_t)(t + 1) * BB * II;
#pragma unroll
            for (int i = 0; i < 8; i++) {
                const int id = tid + 256 * i, r = id >> 5, ch = id & 31;
                asm volatile("cp.async.ca.shared.global [%0], [%1], 16;\n"
                             :: "r"(sbase + S_XB + r * 528 + ch * 16),
                                "l"((const void*)(xs + (size_t)r * II + ch * 8)));
            }
            asm volatile("cp.async.commit_group;\n");
        }

        // -- LSTM epilogue; publish h(t) fp32 (out) + fp16 (exchange) --
        __half* hb = g_hf + ((size_t)(t & 1) * NN + n) * BB * HH;
        const int4 dur4 = *(const int4*)(fd + t * BB + 4 * ty);
        const int durs[4] = {dur4.x, dur4.y, dur4.z, dur4.w};
#pragma unroll
        for (int r = 0; r < 4; r++) {
            const int b = 4 * ty + r;
            const float4 zh = *(const float4*)(Zs + b * 68 + 4 * tx);  // i,f,o,g
            const float zi  = zh.x + bias4[0];
            const float zf_ = zh.y + bias4[1];
            const float zo  = zh.z + bias4[2];
            const float zg_ = zh.w + bias4[3];

            const bool keep = (n > (durs[r] >> 3));

            const float ig = fast_sigmoid(zi);
            const float fg = fast_sigmoid(zf_);
            const float og = fast_sigmoid(zo);
            const float gg = fast_tanh(zg_);

            float cn = fg * creg[r] + ig * gg;
            cn = keep ? creg[r] : cn;
            creg[r] = cn;
            const float hn = og * fast_tanh(cn);

            out[((size_t)(t * NN + n) * BB + b) * HH + j] = hn;
            hb[b * HH + j] = __float2half(hn);
        }

        __syncthreads();   // Zs reads done; h stores issued by all threads

        if (tid == 0) {
            asm volatile("red.release.gpu.global.add.s32 [%0], %1;"
                         :: "l"(g_flags + t * NN + n), "r"(1) : "memory");
        }

        // -- x-GEMM(t+1) first half: absorbs inter-CTA skew before the spin --
        if (t + 1 < TT) {
            asm volatile("cp.async.wait_group 0;\n" ::: "memory");
            __syncthreads();
#pragma unroll
            for (int ma = 0; ma < 2; ma++)
#pragma unroll
                for (int nf = 0; nf < 2; nf++)
#pragma unroll
                    for (int q = 0; q < 4; q++) acc[ma][nf][q] = 0.f;
            gemm2_acc(acc, sbase, S_XB, S_WXH, S_WXL, a_row, a_kof, b_row, b_kof, 0, 8);
        }
    }
}

// ---------------------------------------------------------------------------
extern "C" void kernel_launch(void* const* d_in, const int* in_sizes, int n_in,
                              void* d_out, int out_size)
{
    const float* x  = (const float*)d_in[0];   // [T,B,I] f32
    const int*   fd = (const int*)  d_in[1];   // [T,B]   i32
    const float* w  = (const float*)d_in[2];   // [N,I+H,4H] f32
    const float* bi = (const float*)d_in[3];   // [N,4H]
    const float* bh = (const float*)d_in[4];   // [N,4H]
    float* out = (float*)d_out;                // [T,N,B,H]

    conv_x<<<4096, 256>>>(x);

    cudaFuncSetAttribute(recur_kernel, cudaFuncAttributeMaxDynamicSharedMemorySize,
                         S_TOT);
    recur_kernel<<<128, 256, S_TOT>>>(w, bi, bh, fd, out);
}

// round 14
// speedup vs baseline: 1.6306x; 1.2964x over previous
#include <cuda_runtime.h>
#include <cuda_fp16.h>
#include <math.h>
#include <stdint.h>

#define TT 256
#define BB 64
#define II 256
#define HH 256
#define NN 8
#define FF 1024   // 4*H

// ---------------- scratch (device globals; no allocs) ----------------
__device__ int g_flags[TT * NN];
__device__ __align__(16) __half g_xf[(size_t)TT * BB * II];   // X fp16 [m][k]
// h exchange, parity double-buffered: [p][n][b][k] fp16
__device__ __align__(16) __half g_hf[2 * NN * BB * HH];

extern __shared__ char dynsmem[];

// ---------------- helpers ----------------
__device__ __forceinline__ uint32_t smem_u32(const void* p) {
    uint32_t a;
    asm("{ .reg .u64 t; cvta.to.shared.u64 t, %1; cvt.u32.u64 %0, t; }" : "=r"(a) : "l"(p));
    return a;
}

__device__ __forceinline__ void ldsm_x4(uint32_t* r, uint32_t addr) {
    asm volatile("ldmatrix.sync.aligned.m8n8.x4.shared.b16 {%0,%1,%2,%3}, [%4];"
                 : "=r"(r[0]), "=r"(r[1]), "=r"(r[2]), "=r"(r[3]) : "r"(addr));
}

__device__ __forceinline__ void mma_f16(float* c, const uint32_t* a,
                                        uint32_t b0, uint32_t b1) {
    asm volatile(
        "mma.sync.aligned.m16n8k16.row.col.f32.f16.f16.f32 "
        "{%0,%1,%2,%3}, {%4,%5,%6,%7}, {%8,%9}, {%0,%1,%2,%3};"
        : "+f"(c[0]), "+f"(c[1]), "+f"(c[2]), "+f"(c[3])
        : "r"(a[0]), "r"(a[1]), "r"(a[2]), "r"(a[3]), "r"(b0), "r"(b1));
}

__device__ __forceinline__ float fast_sigmoid(float x) {
    return __fdividef(1.f, 1.f + __expf(-x));
}
__device__ __forceinline__ float fast_tanh(float x) {
    return 1.f - __fdividef(2.f, __expf(2.f * x) + 1.f);
}

// ---------------------------------------------------------------------------
// conv_x: X fp32 -> fp16. Also zeroes g_flags.
// ---------------------------------------------------------------------------
__global__ __launch_bounds__(256) void conv_x(const float* __restrict__ x) {
    if (blockIdx.x < 8) g_flags[blockIdx.x * 256 + threadIdx.x] = 0;
    const size_t i0 = ((size_t)blockIdx.x * 256 + threadIdx.x) * 4;
    const float4 v = *(const float4*)(x + i0);
    __half hv[4];
    hv[0] = __float2half(v.x); hv[1] = __float2half(v.y);
    hv[2] = __float2half(v.z); hv[3] = __float2half(v.w);
    *reinterpret_cast<uint2*>(g_xf + i0) = *reinterpret_cast<uint2*>(hv);
}

// ---------------------------------------------------------------------------
// recur_kernel: fused persistent LSTM, single-fp16 HMMA (weights AND
// activations plain fp16; one product per operand pair).
// 128 CTAs (jt, n), 256 threads = 8 warps (2 b-halves x 4 c-quarters).
// Step pipeline (R13 structure):
//   ... publish(t-1) -> x-GEMM(t) ks 0-7 (absorbs CTA skew) -> spin(t-1) ->
//   issue HB cp.async -> x-GEMM(t) ks 8-15 (covers HB fetch) -> wait ->
//   h-GEMM -> stage -> prefetch XB(t+1) -> epilogue -> publish(t).
// c ordering: c = 4*hl + gate  ->  f = gate*H + jt*16 + hl.
// ---------------------------------------------------------------------------
#define WSTR   264                  // fp16 elems per smem row (256 + 8 pad)
#define S_WX   0
#define S_WH   33792
#define S_XB   67584
#define S_HB   101376
#define S_ZS   135168               // 64*68*4 = 17408
#define S_TOT  152576

__device__ __forceinline__ void gemm1_acc(
    float acc[2][2][4], uint32_t sbase, uint32_t aB, uint32_t bB,
    int a_row, int a_kof, int b_row, int b_kof,
    int ks_begin, int ks_end)
{
#pragma unroll 4
    for (int ks = ks_begin; ks < ks_end; ks++) {
        const int k0 = ks * 16;
        uint32_t a[2][4], b[4];
#pragma unroll
        for (int ma = 0; ma < 2; ma++)
            ldsm_x4(a[ma], sbase + aB + ((a_row + ma * 16) * WSTR + k0 + a_kof) * 2);
        ldsm_x4(b, sbase + bB + (b_row * WSTR + k0 + b_kof) * 2);
#pragma unroll
        for (int ma = 0; ma < 2; ma++)
#pragma unroll
            for (int nf = 0; nf < 2; nf++)
                mma_f16(acc[ma][nf], a[ma], b[nf * 2], b[nf * 2 + 1]);
    }
}

__global__ __launch_bounds__(256, 1) void recur_kernel(
    const float* __restrict__ w,    // [N, I+H, FF]
    const float* __restrict__ bi,   // [N, FF]
    const float* __restrict__ bh_,  // [N, FF]
    const int*   __restrict__ fd,   // [T*B]
    float* out)                     // [T, N, B, H]
{
    char* sm = dynsmem;
    const uint32_t sbase = smem_u32(sm);
    __half* Wx = (__half*)(sm + S_WX);
    __half* Wh = (__half*)(sm + S_WH);
    float* Zs = (float*)(sm + S_ZS);     // [64][68]

    const int jt = blockIdx.x & 15;
    const int n  = blockIdx.x >> 4;
    const int tid = threadIdx.x;
    const int wid = tid >> 5, lane = tid & 31;
    const int tx = tid & 15;
    const int ty = tid >> 4;

    // warp tiling: mw = b-half (32 rows, 2 ma tiles), nw = c-quarter (16)
    const int mw = wid & 1, nw = wid >> 1;
    const int lrow = lane & 7, lgrp = lane >> 3;
    const int a_row = mw * 32 + (lgrp & 1) * 8 + lrow;   // + ma*16
    const int a_kof = (lgrp >> 1) * 8;
    const int b_row = nw * 16 + (lgrp >> 1) * 8 + lrow;
    const int b_kof = (lgrp & 1) * 8;

    // ---- issue X(0) load first (overlaps weight conversion) ----
    {
#pragma unroll
        for (int i = 0; i < 8; i++) {
            const int id = tid + 256 * i, r = id >> 5, ch = id & 31;
            asm volatile("cp.async.ca.shared.global [%0], [%1], 16;\n"
                         :: "r"(sbase + S_XB + r * 528 + ch * 16),
                            "l"((const void*)(g_xf + (size_t)r * II + ch * 8)));
        }
        asm volatile("cp.async.commit_group;\n");
    }

    // ---- prologue: convert Wx and Wh slices (fp32 -> fp16, K-major) ----
    const float* wx = w + (size_t)n * (II + HH) * FF;            // k in [0,256)
    const float* wh = wx + (size_t)II * FF;                      // k in [256,512)
    for (int i = tid; i < 64 * 256; i += 256) {
        const int k = i >> 6, q = i & 63;
        const int g = q >> 4, hl = q & 15;
        const int c = 4 * hl + g;
        const size_t col = (size_t)g * HH + jt * 16 + hl;
        Wx[c * WSTR + k] = __float2half(wx[(size_t)k * FF + col]);
        Wh[c * WSTR + k] = __float2half(wh[(size_t)k * FF + col]);
    }

    // bias registers: thread's column j, 4 gates
    const int j = jt * 16 + tx;
    float bias4[4];
#pragma unroll
    for (int g = 0; g < 4; g++)
        bias4[g] = bi[(size_t)n * FF + g * HH + j] + bh_[(size_t)n * FF + g * HH + j];

    float creg[4] = {0.f, 0.f, 0.f, 0.f};   // rows b = 4*ty + r
    __syncthreads();                         // weights visible

    // XB(0) ready, then first-half x-GEMM(0)
    asm volatile("cp.async.wait_group 0;\n" ::: "memory");
    __syncthreads();

    float acc[2][2][4];
#pragma unroll
    for (int ma = 0; ma < 2; ma++)
#pragma unroll
        for (int nf = 0; nf < 2; nf++)
#pragma unroll
            for (int q = 0; q < 4; q++) acc[ma][nf][q] = 0.f;
    gemm1_acc(acc, sbase, S_XB, S_WX, a_row, a_kof, b_row, b_kof, 0, 8);

    for (int t = 0; t < TT; t++) {
        if (t > 0) {
            // spin on the branch flag (x-half-1 already absorbed most skew)
            int v;
            do {
                asm volatile("ld.acquire.gpu.global.s32 %0, [%1];"
                             : "=r"(v) : "l"(g_flags + (t - 1) * NN + n));
            } while (v < 16);

            // issue cp.async h(t-1) -> HB; latency covered by x-half-2 below
            const __half* sh = g_hf + ((size_t)((t - 1) & 1) * NN + n) * BB * HH;
#pragma unroll
            for (int i = 0; i < 8; i++) {
                const int id = tid + 256 * i, r = id >> 5, ch = id & 31;
                asm volatile("cp.async.ca.shared.global [%0], [%1], 16;\n"
                             :: "r"(sbase + S_HB + r * 528 + ch * 16),
                                "l"((const void*)(sh + (size_t)r * HH + ch * 8)));
            }
            asm volatile("cp.async.commit_group;\n");
        }

        // -- x-GEMM(t) second half: covers the HB L2 fetch --
        gemm1_acc(acc, sbase, S_XB, S_WX, a_row, a_kof, b_row, b_kof, 8, 16);

        if (t > 0) {
            asm volatile("cp.async.wait_group 0;\n" ::: "memory");
            __syncthreads();
            gemm1_acc(acc, sbase, S_HB, S_WH, a_row, a_kof, b_row, b_kof, 0, 16);
        }

        // -- stage z fragments into Zs[b][c] --
#pragma unroll
        for (int ma = 0; ma < 2; ma++)
#pragma unroll
            for (int nf = 0; nf < 2; nf++) {
                const int row = mw * 32 + ma * 16 + (lane >> 2);
                const int col = nw * 16 + nf * 8 + (lane & 3) * 2;
                *(float2*)(Zs + row * 68 + col) =
                    make_float2(acc[ma][nf][0], acc[ma][nf][1]);
                *(float2*)(Zs + (row + 8) * 68 + col) =
                    make_float2(acc[ma][nf][2], acc[ma][nf][3]);
            }
        __syncthreads();

        // -- prefetch X(t+1) into XB (XB free; consumed later this iteration) --
        if (t + 1 < TT) {
            const __half* xs = g_xf + (size_t)(t + 1) * BB * II;
#pragma unroll
            for (int i = 0; i < 8; i++) {
                const int id = tid + 256 * i, r = id >> 5, ch = id & 31;
                asm volatile("cp.async.ca.shared.global [%0], [%1], 16;\n"
                             :: "r"(sbase + S_XB + r * 528 + ch * 16),
                                "l"((const void*)(xs + (size_t)r * II + ch * 8)));
            }
            asm volatile("cp.async.commit_group;\n");
        }

        // -- LSTM epilogue; publish h(t) fp32 (out) + fp16 (exchange) --
        __half* hb = g_hf + ((size_t)(t & 1) * NN + n) * BB * HH;
        const int4 dur4 = *(const int4*)(fd + t * BB + 4 * ty);
        const int durs[4] = {dur4.x, dur4.y, dur4.z, dur4.w};
#pragma unroll
        for (int r = 0; r < 4; r++) {
            const int b = 4 * ty + r;
            const float4 zh = *(const float4*)(Zs + b * 68 + 4 * tx);  // i,f,o,g
            const float zi  = zh.x + bias4[0];
            const float zf_ = zh.y + bias4[1];
            const float zo  = zh.z + bias4[2];
            const float zg_ = zh.w + bias4[3];

            const bool keep = (n > (durs[r] >> 3));

            const float ig = fast_sigmoid(zi);
            const float fg = fast_sigmoid(zf_);
            const float og = fast_sigmoid(zo);
            const float gg = fast_tanh(zg_);

            float cn = fg * creg[r] + ig * gg;
            cn = keep ? creg[r] : cn;
            creg[r] = cn;
            const float hn = og * fast_tanh(cn);

            out[((size_t)(t * NN + n) * BB + b) * HH + j] = hn;
            hb[b * HH + j] = __float2half(hn);
        }

        __syncthreads();   // Zs reads done; h stores issued by all threads

        if (tid == 0) {
            asm volatile("red.release.gpu.global.add.s32 [%0], %1;"
                         :: "l"(g_flags + t * NN + n), "r"(1) : "memory");
        }

        // -- x-GEMM(t+1) first half: absorbs inter-CTA skew before the spin --
        if (t + 1 < TT) {
            asm volatile("cp.async.wait_group 0;\n" ::: "memory");
            __syncthreads();
#pragma unroll
            for (int ma = 0; ma < 2; ma++)
#pragma unroll
                for (int nf = 0; nf < 2; nf++)
#pragma unroll
                    for (int q = 0; q < 4; q++) acc[ma][nf][q] = 0.f;
            gemm1_acc(acc, sbase, S_XB, S_WX, a_row, a_kof, b_row, b_kof, 0, 8);
        }
    }
}

// ---------------------------------------------------------------------------
extern "C" void kernel_launch(void* const* d_in, const int* in_sizes, int n_in,
                              void* d_out, int out_size)
{
    const float* x  = (const float*)d_in[0];   // [T,B,I] f32
    const int*   fd = (const int*)  d_in[1];   // [T,B]   i32
    const float* w  = (const float*)d_in[2];   // [N,I+H,4H] f32
    const float* bi = (const float*)d_in[3];   // [N,4H]
    const float* bh = (const float*)d_in[4];   // [N,4H]
    float* out = (float*)d_out;                // [T,N,B,H]

    conv_x<<<4096, 256>>>(x);

    cudaFuncSetAttribute(recur_kernel, cudaFuncAttributeMaxDynamicSharedMemorySize,
                         S_TOT);
    recur_kernel<<<128, 256, S_TOT>>>(w, bi, bh, fd, out);
}